// round 13
// baseline (speedup 1.0000x reference)
#include <cuda_runtime.h>
#include <cstdint>

// Problem constants (fixed by the dataset)
constexpr int Bc = 8;
constexpr int Nc = 100000;
constexpr int Ec = 3200000;
constexpr int LOSS_BLOCKS = 196;   // 196*256*2 >= 2*Nc: exactly 2 nodes/thread
constexpr int EDGE_TPB = 512;      // 4 blocks/SM x 512 x 32 regs -> 100% occ

// Scratch (device globals — no allocation allowed in kernel_launch).
// g_net starts ZERO (CUDA zero-init of __device__ globals) and is re-zeroed
// by loss_kernel after reading, so prep never has to touch it.
__device__ __align__(16) float g_heads_t[Nc * Bc];   // heads transposed to (N, 8)
__device__ __align__(16) float g_net[Nc * Bc];       // net_flows, node-major (N, 8)
__device__ float g_partials[LOSS_BLOCKS];            // continuity partial sums
__device__ float g_boundary;                         // boundary-loss sum

__device__ __forceinline__ void red_add_v4(float* p, float4 v) {
    asm volatile("red.global.add.v4.f32 [%0], {%1, %2, %3, %4};"
                 :: "l"(__cvta_generic_to_global(p)),
                    "f"(v.x), "f"(v.y), "f"(v.z), "f"(v.w)
                 : "memory");
}

// Deterministic block reduction helper (valid result on thread 0)
__device__ __forceinline__ float block_reduce(float v) {
    __shared__ float sh[32];
    int lane = threadIdx.x & 31;
    int wid  = threadIdx.x >> 5;
    #pragma unroll
    for (int o = 16; o; o >>= 1) v += __shfl_down_sync(0xffffffffu, v, o);
    if (lane == 0) sh[wid] = v;
    __syncthreads();
    int nw = blockDim.x >> 5;
    v = (threadIdx.x < nw) ? sh[threadIdx.x] : 0.f;
    if (wid == 0) {
        #pragma unroll
        for (int o = 16; o; o >>= 1) v += __shfl_down_sync(0xffffffffu, v, o);
    }
    return v;
}

// ---------------------------------------------------------------------------
// Kernel 1: transpose heads (B,N)->(N,8) ONLY (g_net zeroing is deferred to
// loss_kernel of the same run — see header comment). Half the stores of the
// old prep, and prep is on edge_kernel's critical path.
// ---------------------------------------------------------------------------
__global__ void __launch_bounds__(512)
prep_kernel(const float* __restrict__ heads) {
    cudaTriggerProgrammaticLaunchCompletion();
    int t = blockIdx.x * blockDim.x + threadIdx.x;
    int n = t >> 1;
    int h = t & 1;          // which half: batches 0-3 or 4-7
    if (n >= Nc) return;
    const float* hp = heads + (h * 4) * Nc + n;
    float4 a;
    a.x = hp[0 * Nc];
    a.y = hp[1 * Nc];
    a.z = hp[2 * Nc];
    a.w = hp[3 * Nc];
    reinterpret_cast<float4*>(g_heads_t)[2 * n + h] = a;
}

// ---------------------------------------------------------------------------
// Kernel 2 (PDL secondary of prep): loads ei/ea PRE-sync (independent of
// prep), then griddepsync, then gathers/stores/REDs. Lane-pair decomposition
// (R7): 2 threads/edge, pair shares the gathered 128-B line. At LTS ceiling.
// edge_index is INT32 (JAX x64-disabled: "int64" randint is silently int32).
// ---------------------------------------------------------------------------
__global__ void __launch_bounds__(EDGE_TPB)
edge_kernel(const int* __restrict__ ei,
            const float2* __restrict__ ea,
            float* __restrict__ flows) {
    int t = blockIdx.x * blockDim.x + threadIdx.x;   // grid exact: 2*Ec % 512 == 0
    int e = t >> 1;
    int h = t & 1;          // batch half

    // Pre-dependency work: streaming loads that do NOT depend on prep.
    int s = ei[e];
    int d = ei[Ec + e];
    float cond = ea[e].x;

    cudaTriggerProgrammaticLaunchCompletion();   // let loss_kernel launch early
    cudaGridDependencySynchronize();             // wait for prep's g_heads_t

    const float4* ht = reinterpret_cast<const float4*>(g_heads_t);
    float4 hs = ht[2 * s + h];
    float4 hd = ht[2 * d + h];

    float4 f;
    f.x = cond * (hs.x - hd.x);
    f.y = cond * (hs.y - hd.y);
    f.z = cond * (hs.z - hd.z);
    f.w = cond * (hs.w - hd.w);

    // flows output (B, E): per batch row, same-parity lanes write consecutive e.
    // NOTE: flows = d_out + 3 is only 4B-aligned — scalar stores are mandatory.
    long long b0 = (long long)(4 * h) * Ec + e;
    flows[b0]           = f.x;
    flows[b0 + 1LL*Ec]  = f.y;
    flows[b0 + 2LL*Ec]  = f.z;
    flows[b0 + 3LL*Ec]  = f.w;

    if (s != d) {  // self-edge contributes exactly zero net flow
        red_add_v4(&g_net[s * 8 + 4 * h], f);
        float4 nf = make_float4(-f.x, -f.y, -f.z, -f.w);
        red_add_v4(&g_net[d * 8 + 4 * h], nf);
    }
}

// ---------------------------------------------------------------------------
// Kernel 3 (PDL secondary of edge): boundary block (block 196) runs entirely
// PRE-sync and retires immediately (g_boundary visibility to final_kernel is
// ordered by loss-kernel completion). Continuity blocks load demands pre-sync,
// griddepsync, read g_net, and RE-ZERO it for the next run.
// reservoir_nodes is INT32 (same JAX x64 trap).
// ---------------------------------------------------------------------------
__global__ void __launch_bounds__(256)
loss_kernel(const float* __restrict__ demands,
            const float* __restrict__ heads,
            const int*   __restrict__ res,
            const float* __restrict__ rhead) {
    if (blockIdx.x == LOSS_BLOCKS) {   // boundary: independent of edge_kernel
        cudaTriggerProgrammaticLaunchCompletion();
        float rh = rhead[0];
        float acc = 0.f;
        #pragma unroll
        for (int k = 0; k < 2; k++) {
            int i = threadIdx.x + k * 256;
            int b = i >> 6;            // 8 batches
            int j = i & 63;            // 64 reservoir nodes
            int r = res[j];
            float v = heads[(long long)b * Nc + r] - rh;
            acc += v * v;
        }
        float bsum = block_reduce(acc);
        if (threadIdx.x == 0) g_boundary = bsum;
        return;
    }

    // Pre-dependency: demands loads (input array, independent of edge).
    int n0 = blockIdx.x * blockDim.x + threadIdx.x;          // first node
    int n1 = n0 + LOSS_BLOCKS * (int)blockDim.x;             // second node
    float d0[8], d1[8];
    bool v0 = (n0 < Nc), v1 = (n1 < Nc);
    #pragma unroll
    for (int b = 0; b < 8; b++) d0[b] = v0 ? demands[b * Nc + n0] : 0.f;
    #pragma unroll
    for (int b = 0; b < 8; b++) d1[b] = v1 ? demands[b * Nc + n1] : 0.f;

    cudaTriggerProgrammaticLaunchCompletion();   // let final_kernel launch early
    cudaGridDependencySynchronize();             // wait for edge's g_net

    float4* nf = reinterpret_cast<float4*>(g_net);
    const float4 z = make_float4(0.f, 0.f, 0.f, 0.f);
    float acc = 0.f;
    if (v0) {
        float4 a = nf[2 * n0];
        float4 b = nf[2 * n0 + 1];
        nf[2 * n0]     = z;            // re-zero for the next run
        nf[2 * n0 + 1] = z;
        float v;
        v = a.x - d0[0]; acc += v * v;
        v = a.y - d0[1]; acc += v * v;
        v = a.z - d0[2]; acc += v * v;
        v = a.w - d0[3]; acc += v * v;
        v = b.x - d0[4]; acc += v * v;
        v = b.y - d0[5]; acc += v * v;
        v = b.z - d0[6]; acc += v * v;
        v = b.w - d0[7]; acc += v * v;
    }
    if (v1) {
        float4 a = nf[2 * n1];
        float4 b = nf[2 * n1 + 1];
        nf[2 * n1]     = z;            // re-zero for the next run
        nf[2 * n1 + 1] = z;
        float v;
        v = a.x - d1[0]; acc += v * v;
        v = a.y - d1[1]; acc += v * v;
        v = a.z - d1[2]; acc += v * v;
        v = a.w - d1[3]; acc += v * v;
        v = b.x - d1[4]; acc += v * v;
        v = b.y - d1[5]; acc += v * v;
        v = b.z - d1[6]; acc += v * v;
        v = b.w - d1[7]; acc += v * v;
    }
    float s = block_reduce(acc);
    if (threadIdx.x == 0) g_partials[blockIdx.x] = s;
}

// ---------------------------------------------------------------------------
// Kernel 4 (PDL secondary of loss): sum the 196 partials + boundary sum.
// ---------------------------------------------------------------------------
__global__ void __launch_bounds__(256)
final_kernel(float* __restrict__ out) {
    cudaGridDependencySynchronize();   // wait for loss's partials/boundary
    int tid = threadIdx.x;
    float acc = (tid < LOSS_BLOCKS) ? g_partials[tid] : 0.f;
    float csum = block_reduce(acc);
    if (tid == 0) {
        float c  = csum / (float)(Bc * Nc);
        float bl = g_boundary / (float)(Bc * 64);
        out[0] = c;
        out[1] = bl;
        out[2] = c + bl;  // LAMBDA_PHYSICS = 1.0
    }
}

// ---------------------------------------------------------------------------
// Launch: prep -> edge -> loss -> final, successors launched with
// programmatic stream serialization (PDL) so each overlaps its
// predecessor's drain. Graph-capturable.
// ---------------------------------------------------------------------------
extern "C" void kernel_launch(void* const* d_in, const int* in_sizes, int n_in,
                              void* d_out, int out_size) {
    const float*  node_heads = (const float*)d_in[0];
    const float*  demands    = (const float*)d_in[1];
    const int*    edge_index = (const int*)d_in[2];     // int32!
    const float2* edge_attr  = (const float2*)d_in[3];
    const int*    res_nodes  = (const int*)d_in[4];     // int32!
    const float*  res_head   = (const float*)d_in[5];

    float* out   = (float*)d_out;
    float* flows = out + 3;  // output layout: [c, b, total, flows(8*E)]

    prep_kernel<<<(2 * Nc + 511) / 512, 512>>>(node_heads);

    cudaLaunchAttribute pdl_attr;
    pdl_attr.id = cudaLaunchAttributeProgrammaticStreamSerialization;
    pdl_attr.val.programmaticStreamSerializationAllowed = 1;

    {   // edge_kernel with PDL
        cudaLaunchConfig_t cfg = {};
        cfg.gridDim  = dim3((2 * Ec) / EDGE_TPB);
        cfg.blockDim = dim3(EDGE_TPB);
        cfg.stream   = 0;
        cfg.attrs    = &pdl_attr;
        cfg.numAttrs = 1;
        cudaLaunchKernelEx(&cfg, edge_kernel, edge_index, edge_attr, flows);
    }
    {   // loss_kernel with PDL
        cudaLaunchConfig_t cfg = {};
        cfg.gridDim  = dim3(LOSS_BLOCKS + 1);
        cfg.blockDim = dim3(256);
        cfg.stream   = 0;
        cfg.attrs    = &pdl_attr;
        cfg.numAttrs = 1;
        cudaLaunchKernelEx(&cfg, loss_kernel, demands, node_heads, res_nodes, res_head);
    }
    {   // final_kernel with PDL
        cudaLaunchConfig_t cfg = {};
        cfg.gridDim  = dim3(1);
        cfg.blockDim = dim3(256);
        cfg.stream   = 0;
        cfg.attrs    = &pdl_attr;
        cfg.numAttrs = 1;
        cudaLaunchKernelEx(&cfg, final_kernel, out);
    }
}

// round 14
// speedup vs baseline: 1.0221x; 1.0221x over previous
#include <cuda_runtime.h>
#include <cstdint>

// Problem constants (fixed by the dataset)
constexpr int Bc = 8;
constexpr int Nc = 100000;
constexpr int Ec = 3200000;
constexpr int LOSS_BLOCKS = 196;   // 196*256*2 >= 2*Nc: exactly 2 nodes/thread
constexpr int EDGE_TPB = 512;      // 4 blocks/SM x 512 x 32 regs -> 100% occ

// Scratch (device globals — no allocation allowed in kernel_launch)
__device__ __align__(16) float g_heads_t[Nc * Bc];   // heads transposed to (N, 8)
__device__ __align__(16) float g_net[Nc * Bc];       // net_flows, node-major (N, 8)
__device__ float g_partials[LOSS_BLOCKS];            // continuity partial sums
__device__ float g_boundary;                         // boundary-loss sum

__device__ __forceinline__ void red_add_v4(float* p, float4 v) {
    asm volatile("red.global.add.v4.f32 [%0], {%1, %2, %3, %4};"
                 :: "l"(__cvta_generic_to_global(p)),
                    "f"(v.x), "f"(v.y), "f"(v.z), "f"(v.w)
                 : "memory");
}

// Deterministic block reduction helper (valid result on thread 0)
__device__ __forceinline__ float block_reduce(float v) {
    __shared__ float sh[32];
    int lane = threadIdx.x & 31;
    int wid  = threadIdx.x >> 5;
    #pragma unroll
    for (int o = 16; o; o >>= 1) v += __shfl_down_sync(0xffffffffu, v, o);
    if (lane == 0) sh[wid] = v;
    __syncthreads();
    int nw = blockDim.x >> 5;
    v = (threadIdx.x < nw) ? sh[threadIdx.x] : 0.f;
    if (wid == 0) {
        #pragma unroll
        for (int o = 16; o; o >>= 1) v += __shfl_down_sync(0xffffffffu, v, o);
    }
    return v;
}

// ---------------------------------------------------------------------------
// Kernel 1: transpose heads (B,N)->(N,8) AND zero the net accumulator.
// The zero-stores double as L2 residency priming for edge's REDs (R13 lesson:
// deferring them leaves g_net DRAM-cold and costs +2us on the edge phase).
// ---------------------------------------------------------------------------
__global__ void __launch_bounds__(512)
prep_kernel(const float* __restrict__ heads) {
    cudaTriggerProgrammaticLaunchCompletion();
    int t = blockIdx.x * blockDim.x + threadIdx.x;
    int n = t >> 1;
    int h = t & 1;          // which half: batches 0-3 or 4-7
    if (n >= Nc) return;
    const float* hp = heads + (h * 4) * Nc + n;
    float4 a;
    a.x = hp[0 * Nc];
    a.y = hp[1 * Nc];
    a.z = hp[2 * Nc];
    a.w = hp[3 * Nc];
    reinterpret_cast<float4*>(g_heads_t)[2 * n + h] = a;
    reinterpret_cast<float4*>(g_net)[2 * n + h] = make_float4(0.f, 0.f, 0.f, 0.f);
}

// ---------------------------------------------------------------------------
// Kernel 2 (PDL secondary of prep): loads ei/ea PRE-sync (independent of
// prep), then griddepsync, then gathers/stores/REDs. Lane-pair decomposition
// (R7): 2 threads/edge, pair shares the gathered 128-B line. At LTS ceiling
// (occupancy null-test R11: 85%->100% occ changed nothing).
// edge_index is INT32 (JAX x64-disabled: "int64" randint is silently int32).
// ---------------------------------------------------------------------------
__global__ void __launch_bounds__(EDGE_TPB)
edge_kernel(const int* __restrict__ ei,
            const float2* __restrict__ ea,
            float* __restrict__ flows) {
    int t = blockIdx.x * blockDim.x + threadIdx.x;   // grid exact: 2*Ec % 512 == 0
    int e = t >> 1;
    int h = t & 1;          // batch half

    // Pre-dependency work: streaming loads that do NOT depend on prep.
    int s = ei[e];
    int d = ei[Ec + e];
    float cond = ea[e].x;

    cudaTriggerProgrammaticLaunchCompletion();   // let loss_kernel launch early
    cudaGridDependencySynchronize();             // wait for prep's g_heads_t/g_net

    const float4* ht = reinterpret_cast<const float4*>(g_heads_t);
    float4 hs = ht[2 * s + h];
    float4 hd = ht[2 * d + h];

    float4 f;
    f.x = cond * (hs.x - hd.x);
    f.y = cond * (hs.y - hd.y);
    f.z = cond * (hs.z - hd.z);
    f.w = cond * (hs.w - hd.w);

    // flows output (B, E): per batch row, same-parity lanes write consecutive e.
    // NOTE: flows = d_out + 3 is only 4B-aligned — scalar stores are mandatory.
    long long b0 = (long long)(4 * h) * Ec + e;
    flows[b0]           = f.x;
    flows[b0 + 1LL*Ec]  = f.y;
    flows[b0 + 2LL*Ec]  = f.z;
    flows[b0 + 3LL*Ec]  = f.w;

    if (s != d) {  // self-edge contributes exactly zero net flow
        red_add_v4(&g_net[s * 8 + 4 * h], f);
        float4 nf = make_float4(-f.x, -f.y, -f.z, -f.w);
        red_add_v4(&g_net[d * 8 + 4 * h], nf);
    }
}

// ---------------------------------------------------------------------------
// Kernel 3 (PDL secondary of edge): boundary block (block 196) runs entirely
// PRE-sync and retires immediately (g_boundary visibility to final_kernel is
// ordered by loss-grid completion — final's own griddepsync covers it).
// Continuity blocks load demands pre-sync, griddepsync, then read g_net.
// reservoir_nodes is INT32 (same JAX x64 trap).
// ---------------------------------------------------------------------------
__global__ void __launch_bounds__(256)
loss_kernel(const float* __restrict__ demands,
            const float* __restrict__ heads,
            const int*   __restrict__ res,
            const float* __restrict__ rhead) {
    if (blockIdx.x == LOSS_BLOCKS) {   // boundary: independent of edge_kernel
        cudaTriggerProgrammaticLaunchCompletion();
        float rh = rhead[0];
        float acc = 0.f;
        #pragma unroll
        for (int k = 0; k < 2; k++) {
            int i = threadIdx.x + k * 256;
            int b = i >> 6;            // 8 batches
            int j = i & 63;            // 64 reservoir nodes
            int r = res[j];
            float v = heads[(long long)b * Nc + r] - rh;
            acc += v * v;
        }
        float bsum = block_reduce(acc);
        if (threadIdx.x == 0) g_boundary = bsum;
        return;                        // retire early; no grid sync needed
    }

    // Pre-dependency: demands loads (input array, independent of edge).
    int n0 = blockIdx.x * blockDim.x + threadIdx.x;          // first node
    int n1 = n0 + LOSS_BLOCKS * (int)blockDim.x;             // second node
    float d0[8], d1[8];
    bool v0 = (n0 < Nc), v1 = (n1 < Nc);
    #pragma unroll
    for (int b = 0; b < 8; b++) d0[b] = v0 ? demands[b * Nc + n0] : 0.f;
    #pragma unroll
    for (int b = 0; b < 8; b++) d1[b] = v1 ? demands[b * Nc + n1] : 0.f;

    cudaTriggerProgrammaticLaunchCompletion();   // let final_kernel launch early
    cudaGridDependencySynchronize();             // wait for edge's g_net

    const float4* nf = reinterpret_cast<const float4*>(g_net);
    float acc = 0.f;
    if (v0) {
        float4 a = nf[2 * n0];
        float4 b = nf[2 * n0 + 1];
        float v;
        v = a.x - d0[0]; acc += v * v;
        v = a.y - d0[1]; acc += v * v;
        v = a.z - d0[2]; acc += v * v;
        v = a.w - d0[3]; acc += v * v;
        v = b.x - d0[4]; acc += v * v;
        v = b.y - d0[5]; acc += v * v;
        v = b.z - d0[6]; acc += v * v;
        v = b.w - d0[7]; acc += v * v;
    }
    if (v1) {
        float4 a = nf[2 * n1];
        float4 b = nf[2 * n1 + 1];
        float v;
        v = a.x - d1[0]; acc += v * v;
        v = a.y - d1[1]; acc += v * v;
        v = a.z - d1[2]; acc += v * v;
        v = a.w - d1[3]; acc += v * v;
        v = b.x - d1[4]; acc += v * v;
        v = b.y - d1[5]; acc += v * v;
        v = b.z - d1[6]; acc += v * v;
        v = b.w - d1[7]; acc += v * v;
    }
    float s = block_reduce(acc);
    if (threadIdx.x == 0) g_partials[blockIdx.x] = s;
}

// ---------------------------------------------------------------------------
// Kernel 4 (PDL secondary of loss): sum the 196 partials + boundary sum.
// ---------------------------------------------------------------------------
__global__ void __launch_bounds__(256)
final_kernel(float* __restrict__ out) {
    cudaGridDependencySynchronize();   // wait for loss's partials/boundary
    int tid = threadIdx.x;
    float acc = (tid < LOSS_BLOCKS) ? g_partials[tid] : 0.f;
    float csum = block_reduce(acc);
    if (tid == 0) {
        float c  = csum / (float)(Bc * Nc);
        float bl = g_boundary / (float)(Bc * 64);
        out[0] = c;
        out[1] = bl;
        out[2] = c + bl;  // LAMBDA_PHYSICS = 1.0
    }
}

// ---------------------------------------------------------------------------
// Launch: prep -> edge -> loss -> final, successors launched with
// programmatic stream serialization (PDL) so each overlaps its
// predecessor's drain. Graph-capturable.
// ---------------------------------------------------------------------------
extern "C" void kernel_launch(void* const* d_in, const int* in_sizes, int n_in,
                              void* d_out, int out_size) {
    const float*  node_heads = (const float*)d_in[0];
    const float*  demands    = (const float*)d_in[1];
    const int*    edge_index = (const int*)d_in[2];     // int32!
    const float2* edge_attr  = (const float2*)d_in[3];
    const int*    res_nodes  = (const int*)d_in[4];     // int32!
    const float*  res_head   = (const float*)d_in[5];

    float* out   = (float*)d_out;
    float* flows = out + 3;  // output layout: [c, b, total, flows(8*E)]

    prep_kernel<<<(2 * Nc + 511) / 512, 512>>>(node_heads);

    cudaLaunchAttribute pdl_attr;
    pdl_attr.id = cudaLaunchAttributeProgrammaticStreamSerialization;
    pdl_attr.val.programmaticStreamSerializationAllowed = 1;

    {   // edge_kernel with PDL
        cudaLaunchConfig_t cfg = {};
        cfg.gridDim  = dim3((2 * Ec) / EDGE_TPB);
        cfg.blockDim = dim3(EDGE_TPB);
        cfg.stream   = 0;
        cfg.attrs    = &pdl_attr;
        cfg.numAttrs = 1;
        cudaLaunchKernelEx(&cfg, edge_kernel, edge_index, edge_attr, flows);
    }
    {   // loss_kernel with PDL
        cudaLaunchConfig_t cfg = {};
        cfg.gridDim  = dim3(LOSS_BLOCKS + 1);
        cfg.blockDim = dim3(256);
        cfg.stream   = 0;
        cfg.attrs    = &pdl_attr;
        cfg.numAttrs = 1;
        cudaLaunchKernelEx(&cfg, loss_kernel, demands, node_heads, res_nodes, res_head);
    }
    {   // final_kernel with PDL
        cudaLaunchConfig_t cfg = {};
        cfg.gridDim  = dim3(1);
        cfg.blockDim = dim3(256);
        cfg.stream   = 0;
        cfg.attrs    = &pdl_attr;
        cfg.numAttrs = 1;
        cudaLaunchKernelEx(&cfg, final_kernel, out);
    }
}